// round 2
// baseline (speedup 1.0000x reference)
#include <cuda_runtime.h>

#define DTC (1.0f/64.0f)
#define NSTEPS 64
#define NK 32
#define NRAYS 16384

// Channel-interleaved template: [k][z][y][x] -> float4(c0,c1,c2,c3)
__device__ float4 g_templ[NK * 16 * 16 * 16];

__global__ void transpose_kernel(const float* __restrict__ t) {
    int idx = blockIdx.x * blockDim.x + threadIdx.x;  // over NK*4096
    if (idx >= NK * 4096) return;
    int k = idx >> 12;
    int v = idx & 4095;
    const float* src = t + (size_t)k * 4 * 4096 + v;
    g_templ[idx] = make_float4(src[0], src[4096], src[8192], src[12288]);
}

__global__ void __launch_bounds__(256) raymarch_kernel(
    const float* __restrict__ raypos, const float* __restrict__ raydir,
    const float* __restrict__ tminmax, const float* __restrict__ primpos,
    const float* __restrict__ primrot, const float* __restrict__ primscale,
    float* __restrict__ out)
{
    const int lane = threadIdx.x & 31;
    const int ray  = blockIdx.x * 8 + (threadIdx.x >> 5);

    // lane k handles primitive k (K == 32 == warp width)
    const int k = lane;
    const float px = primpos[k*3+0], py = primpos[k*3+1], pz = primpos[k*3+2];
    const float r00 = primrot[k*9+0], r01 = primrot[k*9+1], r02 = primrot[k*9+2];
    const float r10 = primrot[k*9+3], r11 = primrot[k*9+4], r12 = primrot[k*9+5];
    const float r20 = primrot[k*9+6], r21 = primrot[k*9+7], r22 = primrot[k*9+8];
    const float s0 = primscale[k*3+0], s1 = primscale[k*3+1], s2 = primscale[k*3+2];

    const float rpx = raypos[ray*3+0], rpy = raypos[ray*3+1], rpz = raypos[ray*3+2];
    const float rdx = raydir[ray*3+0], rdy = raydir[ray*3+1], rdz = raydir[ray*3+2];
    const float tmin = tminmax[ray*2+0], tmax = tminmax[ray*2+1];

    const float4* __restrict__ tk = g_templ + k * 4096;

    float rgb0 = 0.f, rgb1 = 0.f, rgb2 = 0.f, alpha = 0.f;

    for (int i = 0; i < NSTEPS; i++) {
        float t = fmaf((float)i, DTC, tmin);
        if (t >= tmax) break;            // contrib would be 0 for all later steps
        float wx = fmaf(rdx, t, rpx) - px;
        float wy = fmaf(rdy, t, rpy) - py;
        float wz = fmaf(rdz, t, rpz) - pz;
        // yloc_i = primscale_i * sum_j rot[i][j] * xl_j
        float y0 = s0 * fmaf(r00, wx, fmaf(r01, wy, r02 * wz));
        float y1 = s1 * fmaf(r10, wx, fmaf(r11, wy, r12 * wz));
        float y2 = s2 * fmaf(r20, wx, fmaf(r21, wy, r22 * wz));
        bool inside = fmaxf(fmaxf(fabsf(y0), fabsf(y1)), fabsf(y2)) <= 1.0f;

        if (__ballot_sync(0xffffffffu, inside)) {
            float sr = 0.f, sg = 0.f, sb = 0.f, sa = 0.f;
            if (inside) {
                // y0 -> z, y1 -> y, y2 -> x grid axes
                float gz = fmaf(y0, 7.5f, 7.5f);
                float gy = fmaf(y1, 7.5f, 7.5f);
                float gx = fmaf(y2, 7.5f, 7.5f);
                int iz = min(14, max(0, (int)floorf(gz)));
                int iy = min(14, max(0, (int)floorf(gy)));
                int ix = min(14, max(0, (int)floorf(gx)));
                float fz = fminf(fmaxf(gz - (float)iz, 0.f), 1.f);
                float fy = fminf(fmaxf(gy - (float)iy, 0.f), 1.f);
                float fx = fminf(fmaxf(gx - (float)ix, 0.f), 1.f);

                const float4* p = tk + iz * 256 + iy * 16 + ix;
                float4 c000 = __ldg(p +   0), c001 = __ldg(p +   1);
                float4 c010 = __ldg(p +  16), c011 = __ldg(p +  17);
                float4 c100 = __ldg(p + 256), c101 = __ldg(p + 257);
                float4 c110 = __ldg(p + 272), c111 = __ldg(p + 273);

                #define LERP4(r, a, b, f) \
                    r.x = fmaf(f, b.x - a.x, a.x); r.y = fmaf(f, b.y - a.y, a.y); \
                    r.z = fmaf(f, b.z - a.z, a.z); r.w = fmaf(f, b.w - a.w, a.w);
                float4 c00, c01, c10, c11, c0, c1, cc;
                LERP4(c00, c000, c001, fx); LERP4(c01, c010, c011, fx);
                LERP4(c10, c100, c101, fx); LERP4(c11, c110, c111, fx);
                LERP4(c0, c00, c01, fy);    LERP4(c1, c10, c11, fy);
                LERP4(cc, c0, c1, fz);
                sr = cc.x; sg = cc.y; sb = cc.z; sa = cc.w;
            }
            // warp sum over primitives
            #pragma unroll
            for (int off = 16; off; off >>= 1) {
                sr += __shfl_xor_sync(0xffffffffu, sr, off);
                sg += __shfl_xor_sync(0xffffffffu, sg, off);
                sb += __shfl_xor_sync(0xffffffffu, sb, off);
                sa += __shfl_xor_sync(0xffffffffu, sa, off);
            }
            // sa >= 0 always (softplus template alpha), so only clamp the top
            float na = fminf(fmaf(sa, DTC, alpha), 1.0f);
            float contrib = na - alpha;
            rgb0 = fmaf(sr, contrib, rgb0);
            rgb1 = fmaf(sg, contrib, rgb1);
            rgb2 = fmaf(sb, contrib, rgb2);
            alpha = na;
            if (alpha >= 1.0f) break;    // monotone alpha: no further contribution
        }
    }

    if (lane == 0) {
        // rayrgb (3 planes), rayalpha (1 plane), rayrgba (4 planes)
        out[0 * NRAYS + ray] = rgb0;
        out[1 * NRAYS + ray] = rgb1;
        out[2 * NRAYS + ray] = rgb2;
        out[3 * NRAYS + ray] = alpha;
        out[4 * NRAYS + ray] = rgb0;
        out[5 * NRAYS + ray] = rgb1;
        out[6 * NRAYS + ray] = rgb2;
        out[7 * NRAYS + ray] = alpha;
    }
}

extern "C" void kernel_launch(void* const* d_in, const int* in_sizes, int n_in,
                              void* d_out, int out_size) {
    const float* raypos    = (const float*)d_in[0];
    const float* raydir    = (const float*)d_in[1];
    const float* tminmax   = (const float*)d_in[2];
    const float* primpos   = (const float*)d_in[3];
    const float* primrot   = (const float*)d_in[4];
    const float* primscale = (const float*)d_in[5];
    const float* templ     = (const float*)d_in[6];
    float* out = (float*)d_out;

    transpose_kernel<<<(NK * 4096 + 255) / 256, 256>>>(templ);
    raymarch_kernel<<<NRAYS / 8, 256>>>(raypos, raydir, tminmax,
                                        primpos, primrot, primscale, out);
}

// round 3
// speedup vs baseline: 1.2022x; 1.2022x over previous
#include <cuda_runtime.h>
#include <cuda_fp16.h>

#define DTC (1.0f/64.0f)
#define VOLR 64.0f
#define NSTEPS 64
#define NK 32
#define NRAYS 16384

// Pair-duplicated fp16 template: entry (k,z,y,x) = 8 halves (16B):
// {c0[x],c0[x+1], c1[x],c1[x+1], c2[x],c2[x+1], c3[x],c3[x+1]}
__device__ uint4 g_templ[NK * 16 * 16 * 16];

__global__ void repack_kernel(const float* __restrict__ t) {
    int idx = blockIdx.x * blockDim.x + threadIdx.x;  // over NK*4096 voxels
    if (idx >= NK * 4096) return;
    int k = idx >> 12;
    int v = idx & 4095;          // z*256 + y*16 + x
    int x = v & 15;
    int x1 = (x < 15) ? 1 : 0;   // clamp pair at the edge (never read when x==15)
    const float* src = t + (size_t)k * 4 * 4096 + v;
    __half h[8];
    #pragma unroll
    for (int c = 0; c < 4; c++) {
        h[2*c + 0] = __float2half_rn(src[c * 4096]);
        h[2*c + 1] = __float2half_rn(src[c * 4096 + x1]);
    }
    g_templ[idx] = *reinterpret_cast<uint4*>(h);
}

__global__ void __launch_bounds__(256) raymarch_kernel(
    const float* __restrict__ raypos, const float* __restrict__ raydir,
    const float* __restrict__ tminmax, const float* __restrict__ primpos,
    const float* __restrict__ primrot, const float* __restrict__ primscale,
    float* __restrict__ out)
{
    const int lane = threadIdx.x & 31;
    const int ray  = blockIdx.x * 8 + (threadIdx.x >> 5);
    const unsigned FULL = 0xffffffffu;

    // lane k handles primitive k (K == 32 == warp width)
    const int k = lane;
    const float px = primpos[k*3+0], py = primpos[k*3+1], pz = primpos[k*3+2];
    const float r00 = primrot[k*9+0], r01 = primrot[k*9+1], r02 = primrot[k*9+2];
    const float r10 = primrot[k*9+3], r11 = primrot[k*9+4], r12 = primrot[k*9+5];
    const float r20 = primrot[k*9+6], r21 = primrot[k*9+7], r22 = primrot[k*9+8];
    const float s0 = primscale[k*3+0], s1 = primscale[k*3+1], s2 = primscale[k*3+2];

    const float rpx = raypos[ray*3+0], rpy = raypos[ray*3+1], rpz = raypos[ray*3+2];
    const float rdx = raydir[ray*3+0], rdy = raydir[ray*3+1], rdz = raydir[ray*3+2];
    const float tmin = tminmax[ray*2+0], tmax = tminmax[ray*2+1];

    // Affine yloc: y(t) = b + t*d  (per lane / primitive)
    const float wx = rpx - px, wy = rpy - py, wz = rpz - pz;
    const float b0 = s0 * fmaf(r00, wx, fmaf(r01, wy, r02 * wz));
    const float b1 = s1 * fmaf(r10, wx, fmaf(r11, wy, r12 * wz));
    const float b2 = s2 * fmaf(r20, wx, fmaf(r21, wy, r22 * wz));
    const float d0 = s0 * fmaf(r00, rdx, fmaf(r01, rdy, r02 * rdz));
    const float d1 = s1 * fmaf(r10, rdx, fmaf(r11, rdy, r12 * rdz));
    const float d2 = s2 * fmaf(r20, rdx, fmaf(r21, rdy, r22 * rdz));

    // Slab interval per lane: t where |y(t)| <= 1 on all axes (conservative,
    // widened by 1 step; exact per-step test still applied in the loop).
    float ta = -1e30f, tb = 1e30f;
    {
        const float bb[3] = {b0, b1, b2};
        const float dd[3] = {d0, d1, d2};
        #pragma unroll
        for (int a = 0; a < 3; a++) {
            float b = bb[a], d = dd[a];
            if (fabsf(d) < 1e-12f) {
                if (fabsf(b) > 1.0f) { ta = 1e30f; tb = -1e30f; }
            } else {
                float inv = 1.0f / d;
                float t0 = (-1.0f - b) * inv;
                float t1 = ( 1.0f - b) * inv;
                float lo = fminf(t0, t1), hi = fmaxf(t0, t1);
                ta = fmaxf(ta, lo); tb = fminf(tb, hi);
            }
        }
    }
    int ia, ib;
    if (ta > tb) { ia = NSTEPS; ib = -1; }
    else {
        float iaf = floorf((ta - tmin) * VOLR) - 1.0f;
        float ibf = ceilf((tb - tmin) * VOLR) + 1.0f;
        ia = (int)fminf(fmaxf(iaf, 0.0f), (float)NSTEPS);
        ib = (int)fminf(fmaxf(ibf, -1.0f), (float)(NSTEPS - 1));
    }
    int i_start = ia, i_end = ib;
    #pragma unroll
    for (int off = 16; off; off >>= 1) {
        i_start = min(i_start, __shfl_xor_sync(FULL, i_start, off));
        i_end   = max(i_end,   __shfl_xor_sync(FULL, i_end,   off));
    }

    const uint4* __restrict__ tk = g_templ + (k << 12);
    const int c = lane & 3;

    float acc = 0.f;     // this lane accumulates channel (lane&3)
    float alpha = 0.f;

    for (int i = i_start; i <= i_end; i++) {
        float t = fmaf((float)i, DTC, tmin);
        if (t >= tmax) break;            // zero contribution from here on (per-ray uniform)
        float y0 = fmaf(t, d0, b0);
        float y1 = fmaf(t, d1, b1);
        float y2 = fmaf(t, d2, b2);
        bool inside = fmaxf(fmaxf(fabsf(y0), fabsf(y1)), fabsf(y2)) <= 1.0f;

        if (__ballot_sync(FULL, inside)) {
            float v0 = 0.f, v1 = 0.f, v2 = 0.f, v3 = 0.f;
            if (inside) {
                // y0 -> z, y1 -> y, y2 -> x grid axes
                float gz = fmaf(y0, 7.5f, 7.5f);
                float gy = fmaf(y1, 7.5f, 7.5f);
                float gx = fmaf(y2, 7.5f, 7.5f);
                int iz = min(14, max(0, (int)floorf(gz)));
                int iy = min(14, max(0, (int)floorf(gy)));
                int ix = min(14, max(0, (int)floorf(gx)));
                float fz = fminf(fmaxf(gz - (float)iz, 0.f), 1.f);
                float fy = fminf(fmaxf(gy - (float)iy, 0.f), 1.f);
                float fx = fminf(fmaxf(gx - (float)ix, 0.f), 1.f);

                const uint4* p = tk + (iz << 8) + (iy << 4) + ix;
                uint4 e00 = __ldg(p);            // (z0,y0)
                uint4 e01 = __ldg(p + 16);       // (z0,y1)
                uint4 e10 = __ldg(p + 256);      // (z1,y0)
                uint4 e11 = __ldg(p + 272);      // (z1,y1)

                // x-lerp each row (4 channels), from half2 pairs
                #define XLERP(dst, e)                                            \
                {                                                                \
                    float2 p0 = __half22float2(*(const __half2*)&(e).x);         \
                    float2 p1 = __half22float2(*(const __half2*)&(e).y);         \
                    float2 p2 = __half22float2(*(const __half2*)&(e).z);         \
                    float2 p3 = __half22float2(*(const __half2*)&(e).w);         \
                    dst.x = fmaf(fx, p0.y - p0.x, p0.x);                         \
                    dst.y = fmaf(fx, p1.y - p1.x, p1.x);                         \
                    dst.z = fmaf(fx, p2.y - p2.x, p2.x);                         \
                    dst.w = fmaf(fx, p3.y - p3.x, p3.x);                         \
                }
                float4 r00v, r01v, r10v, r11v;
                XLERP(r00v, e00); XLERP(r01v, e01);
                XLERP(r10v, e10); XLERP(r11v, e11);

                float4 rz0, rz1;
                rz0.x = fmaf(fy, r01v.x - r00v.x, r00v.x);
                rz0.y = fmaf(fy, r01v.y - r00v.y, r00v.y);
                rz0.z = fmaf(fy, r01v.z - r00v.z, r00v.z);
                rz0.w = fmaf(fy, r01v.w - r00v.w, r00v.w);
                rz1.x = fmaf(fy, r11v.x - r10v.x, r10v.x);
                rz1.y = fmaf(fy, r11v.y - r10v.y, r10v.y);
                rz1.z = fmaf(fy, r11v.z - r10v.z, r10v.z);
                rz1.w = fmaf(fy, r11v.w - r10v.w, r10v.w);

                v0 = fmaf(fz, rz1.x - rz0.x, rz0.x);
                v1 = fmaf(fz, rz1.y - rz0.y, rz0.y);
                v2 = fmaf(fz, rz1.z - rz0.z, rz0.z);
                v3 = fmaf(fz, rz1.w - rz0.w, rz0.w);
            }
            // stage 1: butterfly 16/8/4 on all 4 channels -> lane l holds
            // partial sums over lanes with equal (l & 3)
            #pragma unroll
            for (int off = 16; off >= 4; off >>= 1) {
                v0 += __shfl_xor_sync(FULL, v0, off);
                v1 += __shfl_xor_sync(FULL, v1, off);
                v2 += __shfl_xor_sync(FULL, v2, off);
                v3 += __shfl_xor_sync(FULL, v3, off);
            }
            // stage 2: 4x4 transpose-gather: lane l ends with full sum of channel (l&3)
            float own = (c==0)?v0:(c==1)?v1:(c==2)?v2:v3;
            float s1f = (c==0)?v1:(c==1)?v0:(c==2)?v3:v2;   // v[c^1]
            float s2f = (c==0)?v2:(c==1)?v3:(c==2)?v0:v1;   // v[c^2]
            float s3f = (c==0)?v3:(c==1)?v2:(c==2)?v1:v0;   // v[c^3]
            float S = (own + __shfl_xor_sync(FULL, s1f, 1))
                    + (__shfl_xor_sync(FULL, s2f, 2) + __shfl_xor_sync(FULL, s3f, 3));
            float sa = __shfl_sync(FULL, S, 3);             // alpha-channel sum

            // sa >= 0 (softplus alpha), so only clamp the top; alpha monotone
            float na = fminf(fmaf(sa, DTC, alpha), 1.0f);
            float contrib = na - alpha;
            acc = fmaf(S, contrib, acc);
            alpha = na;
            if (alpha >= 1.0f) break;    // no further contribution (uniform)
        }
    }

    // planes: [0..2]=rgb, [3]=alpha, [4..6]=rgb, [7]=alpha
    if (lane < 3) {
        out[lane * NRAYS + ray]       = acc;
        out[(4 + lane) * NRAYS + ray] = acc;
    } else if (lane == 3) {
        out[3 * NRAYS + ray] = alpha;
        out[7 * NRAYS + ray] = alpha;
    }
}

extern "C" void kernel_launch(void* const* d_in, const int* in_sizes, int n_in,
                              void* d_out, int out_size) {
    const float* raypos    = (const float*)d_in[0];
    const float* raydir    = (const float*)d_in[1];
    const float* tminmax   = (const float*)d_in[2];
    const float* primpos   = (const float*)d_in[3];
    const float* primrot   = (const float*)d_in[4];
    const float* primscale = (const float*)d_in[5];
    const float* templ     = (const float*)d_in[6];
    float* out = (float*)d_out;

    repack_kernel<<<(NK * 4096 + 255) / 256, 256>>>(templ);
    raymarch_kernel<<<NRAYS / 8, 256>>>(raypos, raydir, tminmax,
                                        primpos, primrot, primscale, out);
}

// round 5
// speedup vs baseline: 1.3596x; 1.1310x over previous
#include <cuda_runtime.h>
#include <cuda_fp16.h>

#define DTC (1.0f/64.0f)
#define VOLR 64.0f
#define NSTEPS 64
#define NK 32
#define NRAYS 16384

// Pair-duplicated fp16 template: entry (k,z,y,x) = 8 halves (16B):
// {c0[x],c0[x+1], c1[x],c1[x+1], c2[x],c2[x+1], c3[x],c3[x+1]}
__device__ uint4 g_templ[NK * 16 * 16 * 16];

__global__ void repack_kernel(const float* __restrict__ t) {
    int idx = blockIdx.x * blockDim.x + threadIdx.x;  // over NK*4096 voxels
    if (idx >= NK * 4096) return;
    int k = idx >> 12;
    int v = idx & 4095;          // z*256 + y*16 + x
    int x = v & 15;
    int x1 = (x < 15) ? 1 : 0;   // clamp pair at the edge (never read when x==15)
    const float* src = t + (size_t)k * 4 * 4096 + v;
    __half h[8];
    #pragma unroll
    for (int c = 0; c < 4; c++) {
        h[2*c + 0] = __float2half_rn(src[c * 4096]);
        h[2*c + 1] = __float2half_rn(src[c * 4096 + x1]);
    }
    g_templ[idx] = *reinterpret_cast<uint4*>(h);
}

__device__ __forceinline__ float warp_sum(float v) {
    #pragma unroll
    for (int off = 16; off; off >>= 1)
        v += __shfl_xor_sync(0xffffffffu, v, off);
    return v;
}

__global__ void __launch_bounds__(256) raymarch_kernel(
    const float* __restrict__ raypos, const float* __restrict__ raydir,
    const float* __restrict__ tminmax, const float* __restrict__ primpos,
    const float* __restrict__ primrot, const float* __restrict__ primscale,
    float* __restrict__ out)
{
    const int lane = threadIdx.x & 31;
    const int ray  = blockIdx.x * 8 + (threadIdx.x >> 5);
    const unsigned FULL = 0xffffffffu;

    // lane k handles primitive k (K == 32 == warp width)
    const int k = lane;
    const float px = primpos[k*3+0], py = primpos[k*3+1], pz = primpos[k*3+2];
    const float r00 = primrot[k*9+0], r01 = primrot[k*9+1], r02 = primrot[k*9+2];
    const float r10 = primrot[k*9+3], r11 = primrot[k*9+4], r12 = primrot[k*9+5];
    const float r20 = primrot[k*9+6], r21 = primrot[k*9+7], r22 = primrot[k*9+8];
    const float s0 = primscale[k*3+0], s1 = primscale[k*3+1], s2 = primscale[k*3+2];

    const float rpx = raypos[ray*3+0], rpy = raypos[ray*3+1], rpz = raypos[ray*3+2];
    const float rdx = raydir[ray*3+0], rdy = raydir[ray*3+1], rdz = raydir[ray*3+2];
    const float tmin = tminmax[ray*2+0], tmax = tminmax[ray*2+1];

    // Affine yloc: y(t) = b + t*d  (per lane / primitive)
    const float wx = rpx - px, wy = rpy - py, wz = rpz - pz;
    const float b0 = s0 * fmaf(r00, wx, fmaf(r01, wy, r02 * wz));
    const float b1 = s1 * fmaf(r10, wx, fmaf(r11, wy, r12 * wz));
    const float b2 = s2 * fmaf(r20, wx, fmaf(r21, wy, r22 * wz));
    const float d0 = s0 * fmaf(r00, rdx, fmaf(r01, rdy, r02 * rdz));
    const float d1 = s1 * fmaf(r10, rdx, fmaf(r11, rdy, r12 * rdz));
    const float d2 = s2 * fmaf(r20, rdx, fmaf(r21, rdy, r22 * rdz));

    // Slab interval per lane: t where |y(t)| <= 1 on all axes (conservative,
    // widened by 1 step; exact per-step inside test still applied in loop).
    float ta = -1e30f, tb = 1e30f;
    {
        const float bb[3] = {b0, b1, b2};
        const float dd[3] = {d0, d1, d2};
        #pragma unroll
        for (int a = 0; a < 3; a++) {
            float b = bb[a], d = dd[a];
            if (fabsf(d) < 1e-12f) {
                if (fabsf(b) > 1.0f) { ta = 1e30f; tb = -1e30f; }
            } else {
                float inv = 1.0f / d;
                float t0 = (-1.0f - b) * inv;
                float t1 = ( 1.0f - b) * inv;
                float lo = fminf(t0, t1), hi = fmaxf(t0, t1);
                ta = fmaxf(ta, lo); tb = fminf(tb, hi);
            }
        }
    }
    int ia, ib;
    if (ta > tb) { ia = NSTEPS; ib = -1; }
    else {
        float iaf = floorf((ta - tmin) * VOLR) - 1.0f;
        float ibf = ceilf((tb - tmin) * VOLR) + 1.0f;
        ia = (int)fminf(fmaxf(iaf, 0.0f), (float)NSTEPS);
        ib = (int)fminf(fmaxf(ibf, -1.0f), (float)(NSTEPS - 1));
    }
    int i_start = ia, i_end = ib;
    #pragma unroll
    for (int off = 16; off; off >>= 1) {
        i_start = min(i_start, __shfl_xor_sync(FULL, i_start, off));
        i_end   = max(i_end,   __shfl_xor_sync(FULL, i_end,   off));
    }

    const uint4* __restrict__ tk = g_templ + (k << 12);

    float acc0 = 0.f, acc1 = 0.f, acc2 = 0.f;   // per-lane deferred rgb accum
    float alpha = 0.f;                           // identical across lanes

    for (int i = i_start; i <= i_end; i++) {
        float t = fmaf((float)i, DTC, tmin);
        if (t >= tmax) break;            // per-ray uniform: zero contribution after
        float y0 = fmaf(t, d0, b0);
        float y1 = fmaf(t, d1, b1);
        float y2 = fmaf(t, d2, b2);
        bool inside = fmaxf(fmaxf(fabsf(y0), fabsf(y1)), fabsf(y2)) <= 1.0f;

        float v0 = 0.f, v1 = 0.f, v2 = 0.f, v3 = 0.f;
        if (inside) {
            // y0 -> z, y1 -> y, y2 -> x grid axes
            float gz = fmaf(y0, 7.5f, 7.5f);
            float gy = fmaf(y1, 7.5f, 7.5f);
            float gx = fmaf(y2, 7.5f, 7.5f);
            int iz = min(14, max(0, (int)floorf(gz)));
            int iy = min(14, max(0, (int)floorf(gy)));
            int ix = min(14, max(0, (int)floorf(gx)));
            float fz = fminf(fmaxf(gz - (float)iz, 0.f), 1.f);
            float fy = fminf(fmaxf(gy - (float)iy, 0.f), 1.f);
            float fx = fminf(fmaxf(gx - (float)ix, 0.f), 1.f);

            const uint4* p = tk + (iz << 8) + (iy << 4) + ix;
            uint4 e00 = __ldg(p);            // (z0,y0)
            uint4 e01 = __ldg(p + 16);       // (z0,y1)
            uint4 e10 = __ldg(p + 256);      // (z1,y0)
            uint4 e11 = __ldg(p + 272);      // (z1,y1)

            // x-lerp each row (4 channels), from half2 pairs
            #define XLERP(dst, e)                                            \
            {                                                                \
                float2 p0 = __half22float2(*(const __half2*)&(e).x);         \
                float2 p1 = __half22float2(*(const __half2*)&(e).y);         \
                float2 p2 = __half22float2(*(const __half2*)&(e).z);         \
                float2 p3 = __half22float2(*(const __half2*)&(e).w);         \
                dst.x = fmaf(fx, p0.y - p0.x, p0.x);                         \
                dst.y = fmaf(fx, p1.y - p1.x, p1.x);                         \
                dst.z = fmaf(fx, p2.y - p2.x, p2.x);                         \
                dst.w = fmaf(fx, p3.y - p3.x, p3.x);                         \
            }
            float4 r00v, r01v, r10v, r11v;
            XLERP(r00v, e00); XLERP(r01v, e01);
            XLERP(r10v, e10); XLERP(r11v, e11);

            float4 rz0, rz1;
            rz0.x = fmaf(fy, r01v.x - r00v.x, r00v.x);
            rz0.y = fmaf(fy, r01v.y - r00v.y, r00v.y);
            rz0.z = fmaf(fy, r01v.z - r00v.z, r00v.z);
            rz0.w = fmaf(fy, r01v.w - r00v.w, r00v.w);
            rz1.x = fmaf(fy, r11v.x - r10v.x, r10v.x);
            rz1.y = fmaf(fy, r11v.y - r10v.y, r10v.y);
            rz1.z = fmaf(fy, r11v.z - r10v.z, r10v.z);
            rz1.w = fmaf(fy, r11v.w - r10v.w, r10v.w);

            v0 = fmaf(fz, rz1.x - rz0.x, rz0.x);
            v1 = fmaf(fz, rz1.y - rz0.y, rz0.y);
            v2 = fmaf(fz, rz1.z - rz0.z, rz0.z);
            v3 = fmaf(fz, rz1.w - rz0.w, rz0.w);
        }

        // only alpha needs the per-step cross-lane sum (contrib depends on it)
        float sa = warp_sum(v3);
        // sa >= 0 (softplus alpha), so only clamp the top; alpha monotone
        float na = fminf(fmaf(sa, DTC, alpha), 1.0f);
        float contrib = na - alpha;
        acc0 = fmaf(v0, contrib, acc0);
        acc1 = fmaf(v1, contrib, acc1);
        acc2 = fmaf(v2, contrib, acc2);
        alpha = na;
        if (alpha >= 1.0f) break;        // uniform: no further contribution
    }

    // one-time rgb reduction over primitives (lanes)
    float r0 = warp_sum(acc0);
    float r1 = warp_sum(acc1);
    float r2 = warp_sum(acc2);

    // planes: [0..2]=rgb, [3]=alpha, [4..6]=rgb, [7]=alpha
    if (lane == 0) {
        out[0 * NRAYS + ray] = r0;
        out[1 * NRAYS + ray] = r1;
        out[2 * NRAYS + ray] = r2;
        out[3 * NRAYS + ray] = alpha;
        out[4 * NRAYS + ray] = r0;
        out[5 * NRAYS + ray] = r1;
        out[6 * NRAYS + ray] = r2;
        out[7 * NRAYS + ray] = alpha;
    }
}

extern "C" void kernel_launch(void* const* d_in, const int* in_sizes, int n_in,
                              void* d_out, int out_size) {
    const float* raypos    = (const float*)d_in[0];
    const float* raydir    = (const float*)d_in[1];
    const float* tminmax   = (const float*)d_in[2];
    const float* primpos   = (const float*)d_in[3];
    const float* primrot   = (const float*)d_in[4];
    const float* primscale = (const float*)d_in[5];
    const float* templ     = (const float*)d_in[6];
    float* out = (float*)d_out;

    repack_kernel<<<(NK * 4096 + 255) / 256, 256>>>(templ);
    raymarch_kernel<<<NRAYS / 8, 256>>>(raypos, raydir, tminmax,
                                        primpos, primrot, primscale, out);
}

// round 6
// speedup vs baseline: 1.3641x; 1.0033x over previous
#include <cuda_runtime.h>
#include <cuda_fp16.h>

#define DTC (1.0f/64.0f)
#define VOLR 64.0f
#define NSTEPS 64
#define NK 32
#define NRAYS 16384

// Pair-duplicated fp16 template: entry (k,z,y,x) = 8 halves (16B):
// {c0[x],c0[x+1], c1[x],c1[x+1], c2[x],c2[x+1], c3[x],c3[x+1]}
__device__ uint4 g_templ[NK * 16 * 16 * 16];

__global__ void repack_kernel(const float* __restrict__ t) {
    int idx = blockIdx.x * blockDim.x + threadIdx.x;  // over NK*4096 voxels
    if (idx >= NK * 4096) return;
    int k = idx >> 12;
    int v = idx & 4095;          // z*256 + y*16 + x
    int x = v & 15;
    int x1 = (x < 15) ? 1 : 0;   // clamp pair at the edge (never read when x==15)
    const float* src = t + (size_t)k * 4 * 4096 + v;
    __half h[8];
    #pragma unroll
    for (int c = 0; c < 4; c++) {
        h[2*c + 0] = __float2half_rn(src[c * 4096]);
        h[2*c + 1] = __float2half_rn(src[c * 4096 + x1]);
    }
    g_templ[idx] = *reinterpret_cast<uint4*>(h);
}

__device__ __forceinline__ float warp_sum(float v) {
    #pragma unroll
    for (int off = 16; off; off >>= 1)
        v += __shfl_xor_sync(0xffffffffu, v, off);
    return v;
}

// Trilinear sample of 4 channels at grid coords (gz,gy,gx) in [0,15].
// Returns v0..v3; tk points at this lane's primitive sub-volume.
__device__ __forceinline__ void trilerp(const uint4* __restrict__ tk,
                                        float gz, float gy, float gx,
                                        float& v0, float& v1, float& v2, float& v3)
{
    float izf = fminf(floorf(gz), 14.f);
    float iyf = fminf(floorf(gy), 14.f);
    float ixf = fminf(floorf(gx), 14.f);
    float fz = gz - izf, fy = gy - iyf, fx = gx - ixf;   // in [0,1] by construction
    int iz = (int)izf, iy = (int)iyf, ix = (int)ixf;

    const uint4* p = tk + (iz << 8) + (iy << 4) + ix;
    uint4 e00 = __ldg(p);            // (z0,y0)
    uint4 e01 = __ldg(p + 16);       // (z0,y1)
    uint4 e10 = __ldg(p + 256);      // (z1,y0)
    uint4 e11 = __ldg(p + 272);      // (z1,y1)

    #define XLERP(dst, e)                                            \
    {                                                                \
        float2 p0 = __half22float2(*(const __half2*)&(e).x);         \
        float2 p1 = __half22float2(*(const __half2*)&(e).y);         \
        float2 p2 = __half22float2(*(const __half2*)&(e).z);         \
        float2 p3 = __half22float2(*(const __half2*)&(e).w);         \
        dst.x = fmaf(fx, p0.y - p0.x, p0.x);                         \
        dst.y = fmaf(fx, p1.y - p1.x, p1.x);                         \
        dst.z = fmaf(fx, p2.y - p2.x, p2.x);                         \
        dst.w = fmaf(fx, p3.y - p3.x, p3.x);                         \
    }
    float4 r00v, r01v, r10v, r11v;
    XLERP(r00v, e00); XLERP(r01v, e01);
    XLERP(r10v, e10); XLERP(r11v, e11);
    #undef XLERP

    float4 rz0, rz1;
    rz0.x = fmaf(fy, r01v.x - r00v.x, r00v.x);
    rz0.y = fmaf(fy, r01v.y - r00v.y, r00v.y);
    rz0.z = fmaf(fy, r01v.z - r00v.z, r00v.z);
    rz0.w = fmaf(fy, r01v.w - r00v.w, r00v.w);
    rz1.x = fmaf(fy, r11v.x - r10v.x, r10v.x);
    rz1.y = fmaf(fy, r11v.y - r10v.y, r10v.y);
    rz1.z = fmaf(fy, r11v.z - r10v.z, r10v.z);
    rz1.w = fmaf(fy, r11v.w - r10v.w, r10v.w);

    v0 = fmaf(fz, rz1.x - rz0.x, rz0.x);
    v1 = fmaf(fz, rz1.y - rz0.y, rz0.y);
    v2 = fmaf(fz, rz1.z - rz0.z, rz0.z);
    v3 = fmaf(fz, rz1.w - rz0.w, rz0.w);
}

__global__ void __launch_bounds__(128, 8) raymarch_kernel(
    const float* __restrict__ raypos, const float* __restrict__ raydir,
    const float* __restrict__ tminmax, const float* __restrict__ primpos,
    const float* __restrict__ primrot, const float* __restrict__ primscale,
    float* __restrict__ out)
{
    const int lane = threadIdx.x & 31;
    const int ray  = blockIdx.x * 4 + (threadIdx.x >> 5);
    const unsigned FULL = 0xffffffffu;

    // lane k handles primitive k (K == 32 == warp width)
    const int k = lane;
    const float px = primpos[k*3+0], py = primpos[k*3+1], pz = primpos[k*3+2];
    const float r00 = primrot[k*9+0], r01 = primrot[k*9+1], r02 = primrot[k*9+2];
    const float r10 = primrot[k*9+3], r11 = primrot[k*9+4], r12 = primrot[k*9+5];
    const float r20 = primrot[k*9+6], r21 = primrot[k*9+7], r22 = primrot[k*9+8];
    const float s0 = primscale[k*3+0], s1 = primscale[k*3+1], s2 = primscale[k*3+2];

    const float rpx = raypos[ray*3+0], rpy = raypos[ray*3+1], rpz = raypos[ray*3+2];
    const float rdx = raydir[ray*3+0], rdy = raydir[ray*3+1], rdz = raydir[ray*3+2];
    const float tmin = tminmax[ray*2+0], tmax = tminmax[ray*2+1];

    // Grid-space affine: g(t) = Bg + t*Dg, inside <=> all axes in [0,15]
    const float wx = rpx - px, wy = rpy - py, wz = rpz - pz;
    const float Bz = fmaf(s0 * fmaf(r00, wx, fmaf(r01, wy, r02 * wz)), 7.5f, 7.5f);
    const float By = fmaf(s1 * fmaf(r10, wx, fmaf(r11, wy, r12 * wz)), 7.5f, 7.5f);
    const float Bx = fmaf(s2 * fmaf(r20, wx, fmaf(r21, wy, r22 * wz)), 7.5f, 7.5f);
    const float Dz = 7.5f * (s0 * fmaf(r00, rdx, fmaf(r01, rdy, r02 * rdz)));
    const float Dy = 7.5f * (s1 * fmaf(r10, rdx, fmaf(r11, rdy, r12 * rdz)));
    const float Dx = 7.5f * (s2 * fmaf(r20, rdx, fmaf(r21, rdy, r22 * rdz)));

    // Per-lane slab interval in t for g in [0,15] (conservative, widened 1 step)
    float ta = -1e30f, tb = 1e30f;
    {
        const float BB[3] = {Bz, By, Bx};
        const float DD[3] = {Dz, Dy, Dx};
        #pragma unroll
        for (int a = 0; a < 3; a++) {
            float B = BB[a], D = DD[a];
            if (fabsf(D) < 1e-9f) {
                if (B < 0.f || B > 15.f) { ta = 1e30f; tb = -1e30f; }
            } else {
                float inv = 1.0f / D;
                float t0 = (0.f  - B) * inv;
                float t1 = (15.f - B) * inv;
                float lo = fminf(t0, t1), hi = fmaxf(t0, t1);
                ta = fmaxf(ta, lo); tb = fminf(tb, hi);
            }
        }
    }
    int ia, ib;
    if (ta > tb) { ia = NSTEPS; ib = -1; }
    else {
        float iaf = floorf((ta - tmin) * VOLR) - 1.0f;
        float ibf = ceilf((tb - tmin) * VOLR) + 1.0f;
        ia = (int)fminf(fmaxf(iaf, 0.0f), (float)NSTEPS);
        ib = (int)fminf(fmaxf(ibf, -1.0f), (float)(NSTEPS - 1));
    }
    int i_start = ia, i_end = ib;
    #pragma unroll
    for (int off = 16; off; off >>= 1) {
        i_start = min(i_start, __shfl_xor_sync(FULL, i_start, off));
        i_end   = max(i_end,   __shfl_xor_sync(FULL, i_end,   off));
    }

    // Uniform step limit from tmax: for i < ilim, fmaf(i,DTC,tmin) < tmax (exact)
    int ilim = (int)ceilf((tmax - tmin) * VOLR);
    ilim = max(0, min(ilim, NSTEPS));
    while (ilim > 0 && fmaf((float)(ilim - 1), DTC, tmin) >= tmax) ilim--;
    while (ilim < NSTEPS && fmaf((float)ilim, DTC, tmin) < tmax) ilim++;
    i_end = min(i_end, ilim - 1);

    const uint4* __restrict__ tk = g_templ + (k << 12);

    float acc0 = 0.f, acc1 = 0.f, acc2 = 0.f;   // per-lane deferred rgb accum
    float alpha = 0.f;                           // identical across lanes

    for (int i = i_start; i <= i_end; i += 2) {
        // ---- step A ----
        float tA = fmaf((float)i, DTC, tmin);
        float gzA = fmaf(tA, Dz, Bz), gyA = fmaf(tA, Dy, By), gxA = fmaf(tA, Dx, Bx);
        bool inA = fminf(fminf(gzA, gyA), gxA) >= 0.f &&
                   fmaxf(fmaxf(gzA, gyA), gxA) <= 15.f;
        // ---- step B (predicated on existence) ----
        float tB = fmaf((float)(i + 1), DTC, tmin);
        float gzB = fmaf(tB, Dz, Bz), gyB = fmaf(tB, Dy, By), gxB = fmaf(tB, Dx, Bx);
        bool inB = (i + 1 <= i_end) &&
                   fminf(fminf(gzB, gyB), gxB) >= 0.f &&
                   fmaxf(fmaxf(gzB, gyB), gxB) <= 15.f;

        float a0 = 0.f, a1 = 0.f, a2 = 0.f, a3 = 0.f;
        float c0 = 0.f, c1 = 0.f, c2 = 0.f, c3 = 0.f;
        if (inA) trilerp(tk, gzA, gyA, gxA, a0, a1, a2, a3);
        if (inB) trilerp(tk, gzB, gyB, gxB, c0, c1, c2, c3);

        // two independent alpha reductions, interleaved for latency overlap
        float saA = a3, saB = c3;
        #pragma unroll
        for (int off = 16; off; off >>= 1) {
            saA += __shfl_xor_sync(FULL, saA, off);
            saB += __shfl_xor_sync(FULL, saB, off);
        }

        // sequential clamped compositing (exact reference semantics; sa >= 0)
        float naA = fminf(fmaf(saA, DTC, alpha), 1.0f);
        float ctA = naA - alpha;
        float naB = fminf(fmaf(saB, DTC, naA), 1.0f);
        float ctB = naB - naA;
        acc0 = fmaf(a0, ctA, fmaf(c0, ctB, acc0));
        acc1 = fmaf(a1, ctA, fmaf(c1, ctB, acc1));
        acc2 = fmaf(a2, ctA, fmaf(c2, ctB, acc2));
        alpha = naB;
        if (alpha >= 1.0f) break;        // uniform; further steps are exact no-ops
    }

    // one-time rgb reduction over primitives (lanes)
    float r0 = warp_sum(acc0);
    float r1 = warp_sum(acc1);
    float r2 = warp_sum(acc2);

    // planes: [0..2]=rgb, [3]=alpha, [4..6]=rgb, [7]=alpha
    if (lane == 0) {
        out[0 * NRAYS + ray] = r0;
        out[1 * NRAYS + ray] = r1;
        out[2 * NRAYS + ray] = r2;
        out[3 * NRAYS + ray] = alpha;
        out[4 * NRAYS + ray] = r0;
        out[5 * NRAYS + ray] = r1;
        out[6 * NRAYS + ray] = r2;
        out[7 * NRAYS + ray] = alpha;
    }
}

extern "C" void kernel_launch(void* const* d_in, const int* in_sizes, int n_in,
                              void* d_out, int out_size) {
    const float* raypos    = (const float*)d_in[0];
    const float* raydir    = (const float*)d_in[1];
    const float* tminmax   = (const float*)d_in[2];
    const float* primpos   = (const float*)d_in[3];
    const float* primrot   = (const float*)d_in[4];
    const float* primscale = (const float*)d_in[5];
    const float* templ     = (const float*)d_in[6];
    float* out = (float*)d_out;

    repack_kernel<<<(NK * 4096 + 255) / 256, 256>>>(templ);
    raymarch_kernel<<<NRAYS / 4, 128>>>(raypos, raydir, tminmax,
                                        primpos, primrot, primscale, out);
}

// round 7
// speedup vs baseline: 1.4446x; 1.0590x over previous
#include <cuda_runtime.h>
#include <cuda_fp16.h>

#define DTC (1.0f/64.0f)
#define VOLR 64.0f
#define NSTEPS 64
#define NK 32
#define NRAYS 16384

// Channel-vector fp16 template: entry (k,z,y,x) = 8 halves (16B):
// {c0,c1,c2,c3}@x , {c0,c1,c2,c3}@x+1  (x+1 clamped at edge, never used there)
__device__ uint4 g_templ[NK * 16 * 16 * 16];

__global__ void repack_kernel(const float* __restrict__ t) {
    int idx = blockIdx.x * blockDim.x + threadIdx.x;  // over NK*4096 voxels
    if (idx >= NK * 4096) return;
    int k = idx >> 12;
    int v = idx & 4095;          // z*256 + y*16 + x
    int x = v & 15;
    int x1 = (x < 15) ? 1 : 0;
    const float* src = t + (size_t)k * 4 * 4096 + v;
    __half h[8];
    #pragma unroll
    for (int c = 0; c < 4; c++) {
        h[c]     = __float2half_rn(src[c * 4096]);
        h[4 + c] = __float2half_rn(src[c * 4096 + x1]);
    }
    g_templ[idx] = *reinterpret_cast<uint4*>(h);
}

__device__ __forceinline__ float warp_sum(float v) {
    #pragma unroll
    for (int off = 16; off; off >>= 1)
        v += __shfl_xor_sync(0xffffffffu, v, off);
    return v;
}

// Trilinear sample of 4 channels at grid coords (gz,gy,gx) in [0,15].
// x,y lerps in packed fp16 (HSUB2/HFMA2), z lerp in fp32.
__device__ __forceinline__ void trilerp(const uint4* __restrict__ tk,
                                        float gz, float gy, float gx,
                                        float& v0, float& v1, float& v2, float& v3)
{
    float izf = fminf(floorf(gz), 14.f);
    float iyf = fminf(floorf(gy), 14.f);
    float ixf = fminf(floorf(gx), 14.f);
    float fz = gz - izf, fy = gy - iyf, fx = gx - ixf;   // in [0,1]
    int iz = (int)izf, iy = (int)iyf, ix = (int)ixf;

    __half2 fx2 = __float2half2_rn(fx);
    __half2 fy2 = __float2half2_rn(fy);

    const uint4* p = tk + (iz << 8) + (iy << 4) + ix;
    uint4 e00 = __ldg(p);            // (z0,y0)
    uint4 e01 = __ldg(p + 16);       // (z0,y1)
    uint4 e10 = __ldg(p + 256);      // (z1,y0)
    uint4 e11 = __ldg(p + 272);      // (z1,y1)

    // x-lerp: channels {c0,c1} in a, {c2,c3} in b
    #define XL(e, a, b)                                                      \
    {                                                                        \
        __half2 lo0 = *(const __half2*)&(e).x, lo1 = *(const __half2*)&(e).y;\
        __half2 hi0 = *(const __half2*)&(e).z, hi1 = *(const __half2*)&(e).w;\
        a = __hfma2(fx2, __hsub2(hi0, lo0), lo0);                            \
        b = __hfma2(fx2, __hsub2(hi1, lo1), lo1);                            \
    }
    __half2 a00, b00, a01, b01, a10, b10, a11, b11;
    XL(e00, a00, b00); XL(e01, a01, b01);
    XL(e10, a10, b10); XL(e11, a11, b11);
    #undef XL

    // y-lerp (fp16 packed)
    __half2 z0a = __hfma2(fy2, __hsub2(a01, a00), a00);
    __half2 z0b = __hfma2(fy2, __hsub2(b01, b00), b00);
    __half2 z1a = __hfma2(fy2, __hsub2(a11, a10), a10);
    __half2 z1b = __hfma2(fy2, __hsub2(b11, b10), b10);

    // convert, z-lerp in fp32
    float2 f0a = __half22float2(z0a), f0b = __half22float2(z0b);
    float2 f1a = __half22float2(z1a), f1b = __half22float2(z1b);
    v0 = fmaf(fz, f1a.x - f0a.x, f0a.x);
    v1 = fmaf(fz, f1a.y - f0a.y, f0a.y);
    v2 = fmaf(fz, f1b.x - f0b.x, f0b.x);
    v3 = fmaf(fz, f1b.y - f0b.y, f0b.y);
}

__global__ void __launch_bounds__(128, 8) raymarch_kernel(
    const float* __restrict__ raypos, const float* __restrict__ raydir,
    const float* __restrict__ tminmax, const float* __restrict__ primpos,
    const float* __restrict__ primrot, const float* __restrict__ primscale,
    float* __restrict__ out)
{
    const int lane = threadIdx.x & 31;
    const int ray  = blockIdx.x * 4 + (threadIdx.x >> 5);
    const unsigned FULL = 0xffffffffu;

    // lane k handles primitive k (K == 32 == warp width)
    const int k = lane;
    const float px = primpos[k*3+0], py = primpos[k*3+1], pz = primpos[k*3+2];
    const float r00 = primrot[k*9+0], r01 = primrot[k*9+1], r02 = primrot[k*9+2];
    const float r10 = primrot[k*9+3], r11 = primrot[k*9+4], r12 = primrot[k*9+5];
    const float r20 = primrot[k*9+6], r21 = primrot[k*9+7], r22 = primrot[k*9+8];
    const float s0 = primscale[k*3+0], s1 = primscale[k*3+1], s2 = primscale[k*3+2];

    const float rpx = raypos[ray*3+0], rpy = raypos[ray*3+1], rpz = raypos[ray*3+2];
    const float rdx = raydir[ray*3+0], rdy = raydir[ray*3+1], rdz = raydir[ray*3+2];
    const float tmin = tminmax[ray*2+0], tmax = tminmax[ray*2+1];

    // Grid-space affine: g(t) = Bg + t*Dg, inside <=> all axes in [0,15]
    const float wx = rpx - px, wy = rpy - py, wz = rpz - pz;
    const float Bz = fmaf(s0 * fmaf(r00, wx, fmaf(r01, wy, r02 * wz)), 7.5f, 7.5f);
    const float By = fmaf(s1 * fmaf(r10, wx, fmaf(r11, wy, r12 * wz)), 7.5f, 7.5f);
    const float Bx = fmaf(s2 * fmaf(r20, wx, fmaf(r21, wy, r22 * wz)), 7.5f, 7.5f);
    const float Dz = 7.5f * (s0 * fmaf(r00, rdx, fmaf(r01, rdy, r02 * rdz)));
    const float Dy = 7.5f * (s1 * fmaf(r10, rdx, fmaf(r11, rdy, r12 * rdz)));
    const float Dx = 7.5f * (s2 * fmaf(r20, rdx, fmaf(r21, rdy, r22 * rdz)));

    // Per-lane slab interval in t for g in [0,15] (conservative, widened 1 step)
    float ta = -1e30f, tb = 1e30f;
    {
        const float BB[3] = {Bz, By, Bx};
        const float DD[3] = {Dz, Dy, Dx};
        #pragma unroll
        for (int a = 0; a < 3; a++) {
            float B = BB[a], D = DD[a];
            if (fabsf(D) < 1e-9f) {
                if (B < 0.f || B > 15.f) { ta = 1e30f; tb = -1e30f; }
            } else {
                float inv = 1.0f / D;
                float t0 = (0.f  - B) * inv;
                float t1 = (15.f - B) * inv;
                float lo = fminf(t0, t1), hi = fmaxf(t0, t1);
                ta = fmaxf(ta, lo); tb = fminf(tb, hi);
            }
        }
    }
    int ia, ib;
    if (ta > tb) { ia = NSTEPS; ib = -1; }
    else {
        float iaf = floorf((ta - tmin) * VOLR) - 1.0f;
        float ibf = ceilf((tb - tmin) * VOLR) + 1.0f;
        ia = (int)fminf(fmaxf(iaf, 0.0f), (float)NSTEPS);
        ib = (int)fminf(fmaxf(ibf, -1.0f), (float)(NSTEPS - 1));
    }
    int i_start = ia, i_end = ib;
    #pragma unroll
    for (int off = 16; off; off >>= 1) {
        i_start = min(i_start, __shfl_xor_sync(FULL, i_start, off));
        i_end   = max(i_end,   __shfl_xor_sync(FULL, i_end,   off));
    }

    // Uniform step limit from tmax: i valid iff fmaf(i,DTC,tmin) < tmax (exact fixup)
    int ilim = (int)ceilf((tmax - tmin) * VOLR);
    ilim = max(0, min(ilim, NSTEPS));
    while (ilim > 0 && fmaf((float)(ilim - 1), DTC, tmin) >= tmax) ilim--;
    while (ilim < NSTEPS && fmaf((float)ilim, DTC, tmin) < tmax) ilim++;
    i_end = min(i_end, ilim - 1);

    const uint4* __restrict__ tk = g_templ + (k << 12);

    float acc0 = 0.f, acc1 = 0.f, acc2 = 0.f;   // per-lane deferred rgb accum
    float alpha = 0.f;                           // identical across lanes

    for (int i = i_start; i <= i_end; i += 2) {
        // ---- step A ----
        float tA = fmaf((float)i, DTC, tmin);
        float gzA = fmaf(tA, Dz, Bz), gyA = fmaf(tA, Dy, By), gxA = fmaf(tA, Dx, Bx);
        bool inA = fminf(fminf(gzA, gyA), gxA) >= 0.f &&
                   fmaxf(fmaxf(gzA, gyA), gxA) <= 15.f;
        // ---- step B (predicated on existence) ----
        float tB = fmaf((float)(i + 1), DTC, tmin);
        float gzB = fmaf(tB, Dz, Bz), gyB = fmaf(tB, Dy, By), gxB = fmaf(tB, Dx, Bx);
        bool inB = (i + 1 <= i_end) &&
                   fminf(fminf(gzB, gyB), gxB) >= 0.f &&
                   fmaxf(fmaxf(gzB, gyB), gxB) <= 15.f;

        if (!__ballot_sync(FULL, inA || inB)) continue;  // exact no-op pair

        float a0 = 0.f, a1 = 0.f, a2 = 0.f, a3 = 0.f;
        float c0 = 0.f, c1 = 0.f, c2 = 0.f, c3 = 0.f;
        if (inA) trilerp(tk, gzA, gyA, gxA, a0, a1, a2, a3);
        if (inB) trilerp(tk, gzB, gyB, gxB, c0, c1, c2, c3);

        // two independent alpha reductions, interleaved
        float saA = a3, saB = c3;
        #pragma unroll
        for (int off = 16; off; off >>= 1) {
            saA += __shfl_xor_sync(FULL, saA, off);
            saB += __shfl_xor_sync(FULL, saB, off);
        }

        // sequential clamped compositing (exact reference semantics; sa >= 0)
        float naA = fminf(fmaf(saA, DTC, alpha), 1.0f);
        float ctA = naA - alpha;
        float naB = fminf(fmaf(saB, DTC, naA), 1.0f);
        float ctB = naB - naA;
        acc0 = fmaf(a0, ctA, fmaf(c0, ctB, acc0));
        acc1 = fmaf(a1, ctA, fmaf(c1, ctB, acc1));
        acc2 = fmaf(a2, ctA, fmaf(c2, ctB, acc2));
        alpha = naB;
        if (alpha >= 1.0f) break;        // uniform; further steps are exact no-ops
    }

    // one-time rgb reduction over primitives (lanes)
    float r0 = warp_sum(acc0);
    float r1 = warp_sum(acc1);
    float r2 = warp_sum(acc2);

    // planes: [0..2]=rgb, [3]=alpha, [4..6]=rgb, [7]=alpha
    if (lane == 0) {
        out[0 * NRAYS + ray] = r0;
        out[1 * NRAYS + ray] = r1;
        out[2 * NRAYS + ray] = r2;
        out[3 * NRAYS + ray] = alpha;
        out[4 * NRAYS + ray] = r0;
        out[5 * NRAYS + ray] = r1;
        out[6 * NRAYS + ray] = r2;
        out[7 * NRAYS + ray] = alpha;
    }
}

extern "C" void kernel_launch(void* const* d_in, const int* in_sizes, int n_in,
                              void* d_out, int out_size) {
    const float* raypos    = (const float*)d_in[0];
    const float* raydir    = (const float*)d_in[1];
    const float* tminmax   = (const float*)d_in[2];
    const float* primpos   = (const float*)d_in[3];
    const float* primrot   = (const float*)d_in[4];
    const float* primscale = (const float*)d_in[5];
    const float* templ     = (const float*)d_in[6];
    float* out = (float*)d_out;

    repack_kernel<<<(NK * 4096 + 255) / 256, 256>>>(templ);
    raymarch_kernel<<<NRAYS / 4, 128>>>(raypos, raydir, tminmax,
                                        primpos, primrot, primscale, out);
}